// round 14
// baseline (speedup 1.0000x reference)
#include <cuda_runtime.h>
#include <cuda_fp16.h>
#include <cstdint>

#define J 24
#define TFR 4096
#define BB 32
#define KS 15
#define NT 256

// ---- smem layout (bytes) ----
#define A_ROWS   272
#define A_PITCH  256                 // 128 ch * fp16
#define ASZ      (A_ROWS * A_PITCH)  // 69632
#define SMEM_W   ASZ
#define WT       8192                // per-tap pooled W: 128ch x 32n x fp16
#define SMEM_TOTAL (SMEM_W + 4 * WT)     // 102400 -> 2 CTAs/SM
#define EPI_PITCH 1040               // 260 f32
#define EPI_HB    33280              // 32 co * EPI_PITCH

// scratch
__device__ __half g_x[(size_t)BB * TFR * 768];
__device__ __align__(16) __half g_wt[12 * KS * WT / 2];

// ---------------- helpers ----------------
__device__ __forceinline__ uint32_t smem_u32(const void* p) {
    uint32_t a;
    asm("{ .reg .u64 t; cvta.to.shared.u64 t, %1; cvt.u32.u64 %0, t; }" : "=r"(a) : "l"(p));
    return a;
}
__device__ __forceinline__ void ldsm_x4(uint32_t* r, uint32_t a) {
    asm volatile("ldmatrix.sync.aligned.m8n8.x4.shared.b16 {%0,%1,%2,%3}, [%4];"
                 : "=r"(r[0]), "=r"(r[1]), "=r"(r[2]), "=r"(r[3]) : "r"(a));
}
__device__ __forceinline__ void ldsm_x4t(uint32_t* r, uint32_t a) {
    asm volatile("ldmatrix.sync.aligned.m8n8.x4.trans.shared.b16 {%0,%1,%2,%3}, [%4];"
                 : "=r"(r[0]), "=r"(r[1]), "=r"(r[2]), "=r"(r[3]) : "r"(a));
}
__device__ __forceinline__ void mma_f16(float* d, const uint32_t* a, uint32_t b0, uint32_t b1) {
    asm volatile("mma.sync.aligned.m16n8k16.row.col.f32.f16.f16.f32 "
                 "{%0,%1,%2,%3}, {%4,%5,%6,%7}, {%8,%9}, {%0,%1,%2,%3};"
                 : "+f"(d[0]), "+f"(d[1]), "+f"(d[2]), "+f"(d[3])
                 : "r"(a[0]), "r"(a[1]), "r"(a[2]), "r"(a[3]), "r"(b0), "r"(b1));
}
__device__ __forceinline__ void cp16(uint32_t dst, const void* src, uint32_t srcsz) {
    asm volatile("cp.async.cg.shared.global [%0], [%1], 16, %2;"
                 :: "r"(dst), "l"(src), "r"(srcsz) : "memory");
}
#define CP_COMMIT() asm volatile("cp.async.commit_group;" ::: "memory")
#define CP_WAIT0()  asm volatile("cp.async.wait_group 0;" ::: "memory")

__device__ __forceinline__ int iclamp(int v, int lo, int hi) {
    return v < lo ? lo : (v > hi ? hi : v);
}

// ---------------- pre-pass: transpose x -> fp16 [b][t][ch], vectorized ----------------
__global__ void xprep(const float* __restrict__ x) {
    __shared__ float sx[64][65];
    const int tid = threadIdx.x;                 // 256 threads
    const int t0 = blockIdx.x * 64, ch0 = blockIdx.y * 64, b = blockIdx.z;
    {
        const int row = tid >> 4;
        const int v   = tid & 15;
        #pragma unroll
        for (int pp = 0; pp < 4; ++pp) {
            const int r = pp * 16 + row;
            float4 f = *reinterpret_cast<const float4*>(
                &x[((size_t)b * 768 + ch0 + r) * TFR + t0 + 4 * v]);
            sx[r][4 * v + 0] = f.x;  sx[r][4 * v + 1] = f.y;
            sx[r][4 * v + 2] = f.z;  sx[r][4 * v + 3] = f.w;
        }
    }
    __syncthreads();
    {
        const int lane = tid & 31;
        const int rowq = tid >> 5;
        #pragma unroll
        for (int pp = 0; pp < 8; ++pp) {
            const int tr = pp * 8 + rowq;
            __half2 hv = __floats2half2_rn(sx[2 * lane][tr], sx[2 * lane + 1][tr]);
            *reinterpret_cast<__half2*>(
                &g_x[((size_t)b * TFR + t0 + tr) * 768 + ch0 + 2 * lane]) = hv;
        }
    }
}

// ---------------- pre-pass: pooled masked W -> fp16, [ch][n] swizzled ----------------
__global__ void wprep(const float* __restrict__ w) {
    int idx = blockIdx.x * 256 + threadIdx.x;
    const int total = 12 * KS * 128 * 32;
    if (idx >= total) return;
    int n = idx & 31;         idx >>= 5;
    int r = idx & 127;        idx >>= 7;
    int k = idx % KS;
    int g = idx / KS;
    int jb = iclamp(2 * g - 1, 0, J - 4);
    int ji = jb + (r >> 5), ci = r & 31;
    float v = 0.f;
    #pragma unroll
    for (int h = 0; h < 2; ++h) {
        int j = 2 * g + h;
        int d = ji - j;
        if (d >= -1 && d <= 1)
            v += 0.5f * w[((size_t)(j * 32 + n) * 768 + (size_t)(ji * 32 + ci)) * KS + k];
    }
    size_t off = (size_t)(g * KS + k) * WT
               + r * 64 + ((((uint32_t)n >> 3) ^ ((r >> 1) & 3)) << 4) + (n & 7) * 2;
    *reinterpret_cast<__half*>(reinterpret_cast<char*>(g_wt) + off) = __float2half_rn(v);
}

// ---------------- main: mma.sync pooled conv, M=64/warp, K-split warp groups ----------------
__global__ void __launch_bounds__(NT, 2)
skel_mma(const float* __restrict__ bias, float* __restrict__ out)
{
    extern __shared__ char smem[];
    const uint32_t sb = smem_u32(smem);
    const int tid = threadIdx.x;
    const int l = tid & 31, wrp = tid >> 5;
    const int wg = wrp >> 2;                // K-half: q in [wg*4, wg*4+4)
    const int wm = wrp & 3;                 // frames [wm*64, wm*64+64)
    const int tt = blockIdx.x, g = blockIdx.y, b = blockIdx.z;
    const int t0 = tt * 256;

    const int jb = iclamp(2 * g - 1, 0, J - 4);
    const size_t chb = (size_t)jb * 32;

    // ---- prologue: cp.async A tile (zfill OOB) + W taps 0..3 ----
    #pragma unroll 1
    for (int it = 0; it < 17; ++it) {
        int i = it * NT + tid;                // 0..4351
        int r = i >> 4, u = i & 15;
        int t = t0 - 8 + r;
        uint32_t ok = (t >= 0 && t < TFR) ? 16u : 0u;
        uint32_t dst = sb + r * A_PITCH + (((uint32_t)(u ^ (r & 7))) << 4);
        const __half* src = g_x + (((size_t)b * TFR + t) * 768 + chb + (size_t)u * 8);
        cp16(dst, src, ok);
    }
    #pragma unroll
    for (int kk = 0; kk < 4; ++kk) {
        const char* wsrc = reinterpret_cast<const char*>(g_wt) + (size_t)(g * KS + kk) * WT;
        uint32_t wdst = sb + SMEM_W + kk * WT;
        #pragma unroll
        for (int c = 0; c < 2; ++c) {
            int i = c * NT + tid;
            cp16(wdst + i * 16, wsrc + (size_t)i * 16, 16u);
        }
    }
    CP_COMMIT();

    // per-lane constants
    const int row_off = (l & 7) + ((l >> 3) & 1) * 8;
    const int ca      = (l >> 4) & 1;
    const int bswz    = (row_off >> 1) & 3;
    const uint32_t b_lane0 = row_off * 64 + ((uint32_t)((0 + ca) ^ bswz) << 4);
    const uint32_t b_lane1 = row_off * 64 + ((uint32_t)((2 + ca) ^ bswz) << 4);

    float acc[4][4][4];
    #pragma unroll
    for (int mi = 0; mi < 4; ++mi)
        #pragma unroll
        for (int jf = 0; jf < 4; ++jf)
            #pragma unroll
            for (int e = 0; e < 4; ++e) acc[mi][jf][e] = 0.f;

    // ---- tap loop: 2 taps per sync, 4-stage W ring ----
    #pragma unroll 1
    for (int k = 0; k < KS; k += 2) {
        CP_WAIT0();
        __syncthreads();
        #pragma unroll
        for (int d = 2; d < 4; ++d) {
            int kk = k + d;
            if (kk < KS) {
                const char* wsrc = reinterpret_cast<const char*>(g_wt) + (size_t)(g * KS + kk) * WT;
                uint32_t wdst = sb + SMEM_W + (kk & 3) * WT;
                #pragma unroll
                for (int c = 0; c < 2; ++c) {
                    int i = c * NT + tid;
                    cp16(wdst + i * 16, wsrc + (size_t)i * 16, 16u);
                }
            }
        }
        CP_COMMIT();

        #pragma unroll 1
        for (int d = 0; d < 2; ++d) {
            int kk = k + d;
            if (kk >= KS) break;
            const uint32_t bst = sb + SMEM_W + (kk & 3) * WT;
            #pragma unroll
            for (int ql = 0; ql < 4; ++ql) {
                const int q = wg * 4 + ql;
                uint32_t bf[8];
                ldsm_x4t(bf,     bst + q * 1024 + b_lane0);
                ldsm_x4t(bf + 4, bst + q * 1024 + b_lane1);
                #pragma unroll
                for (int mi = 0; mi < 4; ++mi) {
                    uint32_t ah[4];
                    int row = wm * 64 + mi * 16 + row_off + kk + 1;
                    uint32_t aaddr = sb + row * A_PITCH
                        + ((uint32_t)((2 * q + ca) ^ (row & 7)) << 4);
                    ldsm_x4(ah, aaddr);
                    #pragma unroll
                    for (int jf = 0; jf < 4; ++jf)
                        mma_f16(acc[mi][jf], ah, bf[2 * jf], bf[2 * jf + 1]);
                }
            }
        }
    }

    // ---- epilogue: dump partial sums per K-half, combine, bias+leaky, STG.128 ----
    __syncthreads();
    #pragma unroll
    for (int mi = 0; mi < 4; ++mi)
        #pragma unroll
        for (int jf = 0; jf < 4; ++jf)
            #pragma unroll
            for (int e = 0; e < 4; ++e) {
                int co = 8 * jf + 2 * (l & 3) + (e & 1);
                int fr = wm * 64 + mi * 16 + (l >> 2) + 8 * (e >> 1);
                *reinterpret_cast<float*>(smem + wg * EPI_HB + co * EPI_PITCH + fr * 4)
                    = acc[mi][jf][e];
            }
    __syncthreads();

    {
        int co = tid >> 3;                  // 0..31
        int fs = (tid & 7) * 32;            // 32 frames per thread
        float bsum = 0.5f * (bias[g * 64 + co] + bias[g * 64 + 32 + co]);
        float* obase = out + ((size_t)b * 384 + g * 32 + co) * TFR + t0 + fs;
        #pragma unroll
        for (int u = 0; u < 8; ++u) {
            float4 v0 = *reinterpret_cast<float4*>(smem + co * EPI_PITCH + (fs + 4 * u) * 4);
            float4 v1 = *reinterpret_cast<float4*>(smem + EPI_HB + co * EPI_PITCH + (fs + 4 * u) * 4);
            float4 r;
            r.x = v0.x + v1.x + bsum;
            r.y = v0.y + v1.y + bsum;
            r.z = v0.z + v1.z + bsum;
            r.w = v0.w + v1.w + bsum;
            r.x = (r.x >= 0.f) ? r.x : 0.2f * r.x;
            r.y = (r.y >= 0.f) ? r.y : 0.2f * r.y;
            r.z = (r.z >= 0.f) ? r.z : 0.2f * r.z;
            r.w = (r.w >= 0.f) ? r.w : 0.2f * r.w;
            *reinterpret_cast<float4*>(obase + 4 * u) = r;
        }
    }
}

extern "C" void kernel_launch(void* const* d_in, const int* in_sizes, int n_in,
                              void* d_out, int out_size) {
    const float* x      = (const float*)d_in[0];  // [32, 768, 4096]
    const float* weight = (const float*)d_in[1];  // [768, 768, 15]
    const float* bias   = (const float*)d_in[2];  // [768]
    float* out = (float*)d_out;                   // [32, 384, 4096]

    dim3 tg(TFR / 64, 768 / 64, BB);
    xprep<<<tg, 256>>>(x);

    const int wtotal = 12 * KS * 128 * 32;
    wprep<<<(wtotal + 255) / 256, 256>>>(weight);

    cudaFuncSetAttribute(skel_mma, cudaFuncAttributeMaxDynamicSharedMemorySize, SMEM_TOTAL);
    dim3 grid(TFR / 256, 12, BB);
    skel_mma<<<grid, NT, SMEM_TOTAL>>>(bias, out);
}

// round 15
// speedup vs baseline: 1.0356x; 1.0356x over previous
#include <cuda_runtime.h>
#include <cuda_fp16.h>
#include <cstdint>

#define J 24
#define TFR 4096
#define BB 32
#define KS 15
#define NT 256
#define NITEMS 6144            // 16 tt * 12 g * 32 b
#define GRID_P 296             // 2 CTAs per SM, persistent

// ---- smem layout (bytes) ----
#define A_ROWS   272
#define A_PITCH  256                 // 128 ch * fp16
#define ASZ      (A_ROWS * A_PITCH)  // 69632
#define SMEM_W   ASZ
#define WT       8192                // per-tap pooled W: 128ch x 32n x fp16
#define SMEM_TOTAL (SMEM_W + 4 * WT)     // 102400 -> 2 CTAs/SM
#define EPI_PITCH 1040               // 260 f32 (16-co half lives in W region)

// scratch
__device__ __half g_x[(size_t)BB * TFR * 768];
__device__ __align__(16) __half g_wt[12 * KS * WT / 2];

// ---------------- helpers ----------------
__device__ __forceinline__ uint32_t smem_u32(const void* p) {
    uint32_t a;
    asm("{ .reg .u64 t; cvta.to.shared.u64 t, %1; cvt.u32.u64 %0, t; }" : "=r"(a) : "l"(p));
    return a;
}
__device__ __forceinline__ void ldsm_x4(uint32_t* r, uint32_t a) {
    asm volatile("ldmatrix.sync.aligned.m8n8.x4.shared.b16 {%0,%1,%2,%3}, [%4];"
                 : "=r"(r[0]), "=r"(r[1]), "=r"(r[2]), "=r"(r[3]) : "r"(a));
}
__device__ __forceinline__ void ldsm_x4t(uint32_t* r, uint32_t a) {
    asm volatile("ldmatrix.sync.aligned.m8n8.x4.trans.shared.b16 {%0,%1,%2,%3}, [%4];"
                 : "=r"(r[0]), "=r"(r[1]), "=r"(r[2]), "=r"(r[3]) : "r"(a));
}
__device__ __forceinline__ void mma_f16(float* d, const uint32_t* a, uint32_t b0, uint32_t b1) {
    asm volatile("mma.sync.aligned.m16n8k16.row.col.f32.f16.f16.f32 "
                 "{%0,%1,%2,%3}, {%4,%5,%6,%7}, {%8,%9}, {%0,%1,%2,%3};"
                 : "+f"(d[0]), "+f"(d[1]), "+f"(d[2]), "+f"(d[3])
                 : "r"(a[0]), "r"(a[1]), "r"(a[2]), "r"(a[3]), "r"(b0), "r"(b1));
}
__device__ __forceinline__ void cp16(uint32_t dst, const void* src, uint32_t srcsz) {
    asm volatile("cp.async.cg.shared.global [%0], [%1], 16, %2;"
                 :: "r"(dst), "l"(src), "r"(srcsz) : "memory");
}
#define CP_COMMIT() asm volatile("cp.async.commit_group;" ::: "memory")
#define CP_WAIT0()  asm volatile("cp.async.wait_group 0;" ::: "memory")

__device__ __forceinline__ int iclamp(int v, int lo, int hi) {
    return v < lo ? lo : (v > hi ? hi : v);
}

// ---------------- fused pre-pass: x transpose->fp16 AND pooled W pack ----------------
__global__ void prep(const float* __restrict__ x, const float* __restrict__ w) {
    const int bx = blockIdx.x;
    const int tid = threadIdx.x;
    if (bx < 24576) {
        // xprep: 64x64 transpose tile
        __shared__ float sx[64][65];
        const int tq = bx & 63, rest = bx >> 6;
        const int t0 = tq * 64, ch0 = (rest % 12) * 64, b = rest / 12;
        {
            const int row = tid >> 4, v = tid & 15;
            #pragma unroll
            for (int pp = 0; pp < 4; ++pp) {
                const int r = pp * 16 + row;
                float4 f = *reinterpret_cast<const float4*>(
                    &x[((size_t)b * 768 + ch0 + r) * TFR + t0 + 4 * v]);
                sx[r][4 * v + 0] = f.x;  sx[r][4 * v + 1] = f.y;
                sx[r][4 * v + 2] = f.z;  sx[r][4 * v + 3] = f.w;
            }
        }
        __syncthreads();
        {
            const int lane = tid & 31, rowq = tid >> 5;
            #pragma unroll
            for (int pp = 0; pp < 8; ++pp) {
                const int tr = pp * 8 + rowq;
                __half2 hv = __floats2half2_rn(sx[2 * lane][tr], sx[2 * lane + 1][tr]);
                *reinterpret_cast<__half2*>(
                    &g_x[((size_t)b * TFR + t0 + tr) * 768 + ch0 + 2 * lane]) = hv;
            }
        }
    } else {
        // wprep: pooled masked W -> fp16, [ch][n] swizzled
        int idx = (bx - 24576) * 256 + tid;
        int n = idx & 31;         idx >>= 5;
        int r = idx & 127;        idx >>= 7;
        int k = idx % KS;
        int g = idx / KS;
        int jb = iclamp(2 * g - 1, 0, J - 4);
        int ji = jb + (r >> 5), ci = r & 31;
        float v = 0.f;
        #pragma unroll
        for (int h = 0; h < 2; ++h) {
            int j = 2 * g + h;
            int d = ji - j;
            if (d >= -1 && d <= 1)
                v += 0.5f * w[((size_t)(j * 32 + n) * 768 + (size_t)(ji * 32 + ci)) * KS + k];
        }
        size_t off = (size_t)(g * KS + k) * WT
                   + r * 64 + ((((uint32_t)n >> 3) ^ ((r >> 1) & 3)) << 4) + (n & 7) * 2;
        *reinterpret_cast<__half*>(reinterpret_cast<char*>(g_wt) + off) = __float2half_rn(v);
    }
}

// ---------------- main: persistent mma.sync pooled conv ----------------
__global__ void __launch_bounds__(NT, 2)
skel_mma(const float* __restrict__ bias, float* __restrict__ out)
{
    extern __shared__ char smem[];
    const uint32_t sb = smem_u32(smem);
    const int tid = threadIdx.x;
    const int l = tid & 31, wrp = tid >> 5;   // warp owns frames [wrp*32, wrp*32+32)

    // per-lane constants
    const int row_off = (l & 7) + ((l >> 3) & 1) * 8;
    const int ca      = (l >> 4) & 1;
    const int bswz    = (row_off >> 1) & 3;
    const uint32_t b_lane0 = row_off * 64 + ((uint32_t)((0 + ca) ^ bswz) << 4);
    const uint32_t b_lane1 = row_off * 64 + ((uint32_t)((2 + ca) ^ bswz) << 4);

    auto issueA = [&](int b, int jb, int t0) {
        const __half* xg = g_x + (size_t)jb * 32;
        #pragma unroll 1
        for (int it2 = 0; it2 < 17; ++it2) {
            int i = it2 * NT + tid;                // 0..4351
            int r = i >> 4, u = i & 15;
            int t = t0 - 8 + r;
            uint32_t ok = (t >= 0 && t < TFR) ? 16u : 0u;
            uint32_t dst = sb + r * A_PITCH + (((uint32_t)(u ^ (r & 7))) << 4);
            cp16(dst, xg + (((size_t)b * TFR + t) * 768 + (size_t)u * 8), ok);
        }
    };
    auto issueW = [&](int g, int kk) {
        const char* wsrc = reinterpret_cast<const char*>(g_wt) + (size_t)(g * KS + kk) * WT;
        uint32_t wdst = sb + SMEM_W + (kk & 3) * WT;
        #pragma unroll
        for (int c = 0; c < 2; ++c) {
            int i = c * NT + tid;
            cp16(wdst + i * 16, wsrc + (size_t)i * 16, 16u);
        }
    };

    bool first = true;
    #pragma unroll 1
    for (int item = blockIdx.x; item < NITEMS; item += GRID_P) {
        const int tt = item & 15;
        const int rem = item >> 4;
        const int g = rem % 12, b = rem / 12;
        const int t0 = tt * 256;
        const int jb = iclamp(2 * g - 1, 0, J - 4);

        if (first) {
            issueA(b, jb, t0);
            #pragma unroll
            for (int kk = 0; kk < 4; ++kk) issueW(g, kk);
            CP_COMMIT();
            first = false;
        }

        float acc[2][4][4];
        #pragma unroll
        for (int mi = 0; mi < 2; ++mi)
            #pragma unroll
            for (int jf = 0; jf < 4; ++jf)
                #pragma unroll
                for (int e = 0; e < 4; ++e) acc[mi][jf][e] = 0.f;

        // ---- tap loop: 2 taps per sync, 4-stage W ring (R9 mainloop) ----
        #pragma unroll 1
        for (int k = 0; k < KS; k += 2) {
            CP_WAIT0();
            __syncthreads();
            if (k > 0) {
                #pragma unroll
                for (int d = 2; d < 4; ++d) {
                    int kk = k + d;
                    if (kk < KS) issueW(g, kk);
                }
            }
            CP_COMMIT();

            #pragma unroll 1
            for (int d = 0; d < 2; ++d) {
                int kk = k + d;
                if (kk >= KS) break;
                const uint32_t bst = sb + SMEM_W + (kk & 3) * WT;
                #pragma unroll 1
                for (int q = 0; q < 8; ++q) {
                    uint32_t bf[8];
                    ldsm_x4t(bf,     bst + q * 1024 + b_lane0);
                    ldsm_x4t(bf + 4, bst + q * 1024 + b_lane1);
                    #pragma unroll
                    for (int mi = 0; mi < 2; ++mi) {
                        uint32_t ah[4];
                        int row = wrp * 32 + mi * 16 + row_off + kk + 1;
                        uint32_t aaddr = sb + row * A_PITCH
                            + ((uint32_t)((2 * q + ca) ^ (row & 7)) << 4);
                        ldsm_x4(ah, aaddr);
                        #pragma unroll
                        for (int jf = 0; jf < 4; ++jf)
                            mma_f16(acc[mi][jf], ah, bf[2 * jf], bf[2 * jf + 1]);
                    }
                }
            }
        }

        __syncthreads();   // all ldsm of this item done: A + W regions free

        // ---- prefetch next item's A tile (overlaps epilogue) ----
        const int nitem = item + GRID_P;
        int ng = 0;
        if (nitem < NITEMS) {
            const int ntt = nitem & 15;
            const int nrem = nitem >> 4;
            ng = nrem % 12;
            const int nb = nrem / 12;
            issueA(nb, iclamp(2 * ng - 1, 0, J - 4), ntt * 256);
            CP_COMMIT();
        }

        // ---- epilogue in W region: two 16-co halves ----
        #pragma unroll
        for (int h = 0; h < 2; ++h) {
            #pragma unroll
            for (int mi = 0; mi < 2; ++mi)
                #pragma unroll
                for (int jfl = 0; jfl < 2; ++jfl) {
                    const int jf = 2 * h + jfl;
                    #pragma unroll
                    for (int e = 0; e < 4; ++e) {
                        int col = 8 * jfl + 2 * (l & 3) + (e & 1);
                        int fr  = wrp * 32 + mi * 16 + (l >> 2) + 8 * (e >> 1);
                        *reinterpret_cast<float*>(smem + SMEM_W + col * EPI_PITCH + fr * 4)
                            = acc[mi][jf][e];
                    }
                }
            __syncthreads();
            {
                int col = tid >> 4;                 // 0..15
                int fs  = (tid & 15) * 16;          // 16 frames per thread
                int co  = 16 * h + col;
                float bsum = 0.5f * (bias[g * 64 + co] + bias[g * 64 + 32 + co]);
                float* obase = out + ((size_t)b * 384 + g * 32 + co) * TFR + t0 + fs;
                #pragma unroll
                for (int u = 0; u < 4; ++u) {
                    float4 v = *reinterpret_cast<float4*>(
                        smem + SMEM_W + col * EPI_PITCH + (fs + 4 * u) * 4);
                    float4 r;
                    r.x = v.x + bsum;  r.y = v.y + bsum;
                    r.z = v.z + bsum;  r.w = v.w + bsum;
                    r.x = (r.x >= 0.f) ? r.x : 0.2f * r.x;
                    r.y = (r.y >= 0.f) ? r.y : 0.2f * r.y;
                    r.z = (r.z >= 0.f) ? r.z : 0.2f * r.z;
                    r.w = (r.w >= 0.f) ? r.w : 0.2f * r.w;
                    *reinterpret_cast<float4*>(obase + 4 * u) = r;
                }
            }
            __syncthreads();
        }

        // ---- prefetch next item's W taps 0..3 (W region free again) ----
        if (nitem < NITEMS) {
            #pragma unroll
            for (int kk = 0; kk < 4; ++kk) issueW(ng, kk);
            CP_COMMIT();
        }
    }
}

extern "C" void kernel_launch(void* const* d_in, const int* in_sizes, int n_in,
                              void* d_out, int out_size) {
    const float* x      = (const float*)d_in[0];  // [32, 768, 4096]
    const float* weight = (const float*)d_in[1];  // [768, 768, 15]
    const float* bias   = (const float*)d_in[2];  // [768]
    float* out = (float*)d_out;                   // [32, 384, 4096]

    // fused pre-pass: blocks [0,24576) transpose x; [24576, 24576+2880) pack W
    prep<<<24576 + 2880, 256>>>(x, weight);

    cudaFuncSetAttribute(skel_mma, cudaFuncAttributeMaxDynamicSharedMemorySize, SMEM_TOTAL);
    skel_mma<<<GRID_P, NT, SMEM_TOTAL>>>(bias, out);
}